// round 13
// baseline (speedup 1.0000x reference)
#include <cuda_runtime.h>
#include <cstdint>

#define NUM_CLASSES 7
#define NTHREADS 256
#define NWARPS 8
#define WROWS 64                        // rows per warp-slot (multiple of 4)
#define SLOT_LOG (WROWS * 28)           // 1792
#define SLOT_REP (WROWS * 12)           //  768
#define SLOT_LAB (WROWS * 4)            //  256
#define SLOT_BYTES (SLOT_LOG + SLOT_REP + SLOT_LAB)   // 2816
#define NSTAGES 4
#define WARP_BYTES (NSTAGES * SLOT_BYTES)             // 11264
#define SMEM_DYN (NWARPS * WARP_BYTES)                // 90112 -> 2 blocks/SM
#define NBLOCKS 296                     // 148 SMs * 2 resident
#define CHUNK 8                         // 64-row tiles claimed per steal

__device__ double g_sum = 0.0;
__device__ unsigned int g_done_count = 0;
__device__ unsigned int g_tile = 0;

__device__ __forceinline__ uint32_t smem_u32(const void* p) {
    uint32_t a;
    asm("{ .reg .u64 t; cvta.to.shared.u64 t, %1; cvt.u32.u64 %0, t; }"
        : "=r"(a) : "l"(p));
    return a;
}
__device__ __forceinline__ void mbar_init(uint32_t mbar, uint32_t count) {
    asm volatile("mbarrier.init.shared.b64 [%0], %1;" :: "r"(mbar), "r"(count) : "memory");
}
__device__ __forceinline__ void mbar_expect_tx(uint32_t mbar, uint32_t bytes) {
    asm volatile("mbarrier.arrive.expect_tx.shared.b64 _, [%0], %1;"
                 :: "r"(mbar), "r"(bytes) : "memory");
}
__device__ __forceinline__ void bulk_g2s(uint32_t sdst, const void* gsrc,
                                         uint32_t bytes, uint32_t mbar) {
    asm volatile("cp.async.bulk.shared::cta.global.mbarrier::complete_tx::bytes "
                 "[%0], [%1], %2, [%3];"
                 :: "r"(sdst), "l"(gsrc), "r"(bytes), "r"(mbar) : "memory");
}
__device__ __forceinline__ void mbar_wait(uint32_t mbar, uint32_t parity) {
    asm volatile(
        "{\n\t"
        ".reg .pred P;\n\t"
        "W%=:\n\t"
        "mbarrier.try_wait.parity.acquire.cta.shared::cta.b64 P, [%0], %1, 0x989680;\n\t"
        "@P bra D%=;\n\t"
        "bra W%=;\n\t"
        "D%=:\n\t"
        "}" :: "r"(mbar), "r"(parity) : "memory");
}

__global__ __launch_bounds__(NTHREADS)
void hinge_warp_kernel(const char* __restrict__ logit_g,
                       const char* __restrict__ label_g,
                       const char* __restrict__ repr_g,
                       const float* __restrict__ logit_s,
                       const int* __restrict__ label_s,
                       const int* __restrict__ repr_s,
                       int ntiles, int Bmain, int B,
                       float* __restrict__ out)
{
    extern __shared__ __align__(16) char sbuf[];     // NWARPS * WARP_BYTES
    __shared__ __align__(8) unsigned long long smbar[NWARPS * NSTAGES];

    const int t = threadIdx.x;
    const int w = t >> 5;
    const int lane = t & 31;
    const uint32_t mb_all = smem_u32(&smbar[0]);
    const uint32_t sb_all = smem_u32(sbuf);

    if (t < NWARPS * NSTAGES) mbar_init(mb_all + 8u * t, 1);
    __syncthreads();     // only barrier: after mbar init

    const uint32_t wmb = mb_all + (uint32_t)w * (NSTAGES * 8);
    const uint32_t wsb = sb_all + (uint32_t)w * WARP_BYTES;
    const char* wbp = sbuf + w * WARP_BYTES;

    float acc = 0.0f;
    int ph[NSTAGES] = {0, 0, 0, 0};
    int stile[NSTAGES];
    int cur = 0, end = 0;    // uniform across warp

    // claim the next 64-row tile (chunked steal, warp-uniform)
    auto next_tile = [&]() -> int {
        if (cur == end) {
            int base;
            if (lane == 0) base = (int)atomicAdd(&g_tile, (unsigned)CHUNK);
            base = __shfl_sync(0xffffffffu, base, 0);
            cur = base; end = base + CHUNK;
        }
        return cur++;
    };

    // lane 0 issues bulk copies for tile into stage s of this warp's ring
    auto issue = [&](int s, int tile) {
        if (lane != 0) return;
        const int base_row = tile * WROWS;
        const int rows = min(WROWS, Bmain - base_row);
        const uint32_t lb = (uint32_t)(rows * 28);
        const uint32_t rb = (uint32_t)(rows * 12);
        const uint32_t bb = (uint32_t)(rows * 4);
        const uint32_t mb = wmb + 8u * s;
        const uint32_t sb = wsb + (uint32_t)s * SLOT_BYTES;
        mbar_expect_tx(mb, lb + rb + bb);
        bulk_g2s(sb,                        logit_g + (size_t)base_row * 28, lb, mb);
        bulk_g2s(sb + SLOT_LOG,             repr_g  + (size_t)base_row * 12, rb, mb);
        bulk_g2s(sb + SLOT_LOG + SLOT_REP,  label_g + (size_t)base_row * 4,  bb, mb);
    };

    // prologue: fill all NSTAGES slots
    #pragma unroll
    for (int p = 0; p < NSTAGES; p++) {
        stile[p] = next_tile();
        if (stile[p] < ntiles) issue(p, stile[p]);
    }

    int stage = 0;
    for (;;) {
        const int tile = stile[stage];
        if (tile >= ntiles) break;

        mbar_wait(wmb + 8u * stage, ph[stage]);
        ph[stage] ^= 1;

        const char* bp = wbp + stage * SLOT_BYTES;
        const int rows = min(WROWS, Bmain - tile * WROWS);

        // lane owns local rows 2*lane, 2*lane+1 (rows is a multiple of 4)
        if (2 * lane + 1 < rows) {
            const float2* lp = reinterpret_cast<const float2*>(bp + 56 * lane);
            float2 l[7];
            #pragma unroll
            for (int k = 0; k < 7; k++) l[k] = lp[k];
            const float* lf = reinterpret_cast<const float*>(l);

            const int2* rp = reinterpret_cast<const int2*>(bp + SLOT_LOG + 24 * lane);
            int2 r[3];
            #pragma unroll
            for (int k = 0; k < 3; k++) r[k] = rp[k];
            const int* rv = reinterpret_cast<const int*>(r);

            int2 lab = *reinterpret_cast<const int2*>(bp + SLOT_LOG + SLOT_REP + 8 * lane);
            const int* lbv = reinterpret_cast<const int*>(&lab);

            #pragma unroll
            for (int row = 0; row < 2; row++) {
                unsigned mask = (1u << rv[row * 3 + 0])
                              | (1u << rv[row * 3 + 1])
                              | (1u << rv[row * 3 + 2]);
                float tg = (lbv[row] == 1) ? 1.0f : 0.0f;
                #pragma unroll
                for (int jj = 0; jj < NUM_CLASSES; jj++) {
                    float d = lf[row * NUM_CLASSES + jj] - tg;
                    acc += ((mask >> jj) & 1u) ? fabsf(d) : fmaxf(d, 0.0f);
                }
            }
        }
        __syncwarp();     // all lanes done reading this slot

        // refill this slot from the work queue
        const int ftl = next_tile();
        stile[stage] = ftl;
        if (ftl < ntiles) issue(stage, ftl);

        stage = (stage + 1) & (NSTAGES - 1);
    }

    // remainder rows (B % 4 != 0), direct from gmem
    if (blockIdx.x == 0 && t == 0) {
        for (int row = Bmain; row < B; row++) {
            unsigned mask = (1u << repr_s[(size_t)row * 3 + 0])
                          | (1u << repr_s[(size_t)row * 3 + 1])
                          | (1u << repr_s[(size_t)row * 3 + 2]);
            float tg = (label_s[row] == 1) ? 1.0f : 0.0f;
            for (int jj = 0; jj < NUM_CLASSES; jj++) {
                float d = logit_s[(size_t)row * NUM_CLASSES + jj] - tg;
                acc += ((mask >> jj) & 1u) ? fabsf(d) : fmaxf(d, 0.0f);
            }
        }
    }

    // intra-warp reduce, then block reduce
    #pragma unroll
    for (int o = 16; o > 0; o >>= 1)
        acc += __shfl_down_sync(0xffffffffu, acc, o);

    __shared__ float sred[NWARPS];
    if (lane == 0) sred[w] = acc;
    __syncthreads();

    // tiny epilogue: one f64 atomic per block + last-block scalar writeout
    if (t == 0) {
        float v = 0.0f;
        #pragma unroll
        for (int i = 0; i < NWARPS; i++) v += sred[i];

        atomicAdd(&g_sum, (double)v);
        __threadfence();
        unsigned int prev = atomicAdd(&g_done_count, 1u);
        if (prev == (unsigned)gridDim.x - 1u) {
            double total = atomicAdd(&g_sum, 0.0);
            *out = (float)total;
            g_sum = 0.0;
            g_done_count = 0u;
            g_tile = 0u;      // reset work queue for next graph replay
        }
    }
}

extern "C" void kernel_launch(void* const* d_in, const int* in_sizes, int n_in,
                              void* d_out, int out_size)
{
    // logit is [B,7] fp32 at d_in[0] (largest input, 7-multiple element count).
    const float* logit = (const float*)d_in[0];
    const int B = in_sizes[0] / NUM_CLASSES;

    // Disambiguate label ([B] int32) vs repr_num ([B,3] int32) by element count.
    const int* label;
    const int* repr;
    if (in_sizes[1] == B) {
        label = (const int*)d_in[1];
        repr  = (const int*)d_in[2];
    } else {
        label = (const int*)d_in[2];
        repr  = (const int*)d_in[1];
    }

    const int Bmain = (B / 4) * 4;
    const int ntiles = (Bmain + WROWS - 1) / WROWS;

    static bool attr_set = false;
    if (!attr_set) {
        cudaFuncSetAttribute(hinge_warp_kernel,
                             cudaFuncAttributeMaxDynamicSharedMemorySize, SMEM_DYN);
        attr_set = true;
    }

    hinge_warp_kernel<<<NBLOCKS, NTHREADS, SMEM_DYN>>>(
        (const char*)logit, (const char*)label, (const char*)repr,
        logit, label, repr, ntiles, Bmain, B, (float*)d_out);
}